// round 4
// baseline (speedup 1.0000x reference)
#include <cuda_runtime.h>
#include <cuda_bf16.h>
#include <math.h>

// BlockGCN fused kernel, round 4: x-reuse across k, constant-memory weights,
// f32x2 packed math. out = relu( BN( sum_k conv_k( einsum(x, BnA_k) ) ) + x )

#define NK 3
#define NH 8
#define NV 23
#define NVP 24
#define CG 16
#define NT 256
#define NN 32
#define NC 128
#define TB 16
#define THREADS 368      // 16 t x 23 w

typedef unsigned long long ull;

__device__ __forceinline__ ull fma2(ull a, ull b, ull c) {
    ull d;
    asm("fma.rn.f32x2 %0, %1, %2, %3;" : "=l"(d) : "l"(a), "l"(b), "l"(c));
    return d;
}
__device__ __forceinline__ ull add2(ull a, ull b) {
    ull d;
    asm("add.rn.f32x2 %0, %1, %2;" : "=l"(d) : "l"(a), "l"(b));
    return d;
}
__device__ __forceinline__ ull pack2(float lo, float hi) {
    ull d;
    asm("mov.b64 %0, {%1, %2};" : "=l"(d) : "f"(lo), "f"(hi));
    return d;
}
__device__ __forceinline__ void unpack2(ull v, float& lo, float& hi) {
    asm("mov.b64 {%0, %1}, %2;" : "=f"(lo), "=f"(hi) : "l"(v));
}

// Precompute outputs (device globals; no allocation).
__device__ float g_bna[NK][NH][NV][NVP];       // [k][h][w][v], v padded with 0
__device__ ull   g_ws2[NK * NH * CG * 8];      // pack(ws[o0],ws[o1]) o-pairs, BN folded
__device__ ull   g_bias2[NH * 8];              // folded bias o-pairs

// Constant mirrors (filled by async D2D copy each launch).
__constant__ ull c_ws2[NK * NH * CG * 8];      // 24 KB
__constant__ ull c_bias2[NH * 8];              // 512 B

__global__ void precompute_kernel(const float* __restrict__ emb,
                                  const float* __restrict__ A,
                                  const float* __restrict__ conv_w,
                                  const float* __restrict__ conv_b,
                                  const float* __restrict__ gamma,
                                  const float* __restrict__ beta,
                                  const float* __restrict__ mean,
                                  const float* __restrict__ var,
                                  const int*   __restrict__ hop,
                                  int n_hop)
{
    int b = blockIdx.x;
    int tid = threadIdx.x;
    if (b < NK * NH) {
        int k = b / NH, h = b % NH;
        int w = tid;
        if (w < NV) {
            float Bc[NV], Ac[NV];
            float sB = 0.f, sA = 0.f;
            #pragma unroll
            for (int v = 0; v < NV; v++) {
                float bb = emb[(k * NH + h) * n_hop + hop[v * NV + w]];
                float aa = A[((k * NH + h) * NV + v) * NV + w];
                Bc[v] = bb; Ac[v] = aa;
                sB += bb * bb; sA += aa * aa;
            }
            float iB = 1.f / (sqrtf(sB) + 1e-4f);
            float iA = 1.f / (sqrtf(sA) + 1e-4f);
            #pragma unroll
            for (int v = 0; v < NV; v++)
                g_bna[k][h][w][v] = Bc[v] * iB + Ac[v] * iA;
            g_bna[k][h][w][NV] = 0.f;
        }
    } else {
        // ws2[(k,h,c,q)] = pack(conv_w[row(o0)]*inv[o0], conv_w[row(o1)]*inv[o1])
        for (int idx = tid; idx < NK * NH * CG * 8; idx += blockDim.x) {
            int q = idx % 8;
            int c = (idx / 8) % CG;
            int h = (idx / (8 * CG)) % NH;
            int k = idx / (8 * CG * NH);
            int o0 = 2 * q, o1 = 2 * q + 1;
            int och0 = h * CG + o0, och1 = h * CG + o1;
            float inv0 = gamma[och0] * rsqrtf(var[och0] + 1e-5f);
            float inv1 = gamma[och1] * rsqrtf(var[och1] + 1e-5f);
            float w0 = conv_w[(k * NC + och0) * CG + c] * inv0;
            float w1 = conv_w[(k * NC + och1) * CG + c] * inv1;
            g_ws2[idx] = pack2(w0, w1);
        }
        for (int idx = tid; idx < NH * 8; idx += blockDim.x) {
            int q = idx % 8, h = idx / 8;
            float bv[2];
            #pragma unroll
            for (int j = 0; j < 2; j++) {
                int och = h * CG + 2 * q + j;
                float inv = gamma[och] * rsqrtf(var[och] + 1e-5f);
                float sb = conv_b[och] + conv_b[NC + och] + conv_b[2 * NC + och];
                bv[j] = sb * inv + beta[och] - mean[och] * inv;
            }
            g_bias2[idx] = pack2(bv[0], bv[1]);
        }
    }
}

__global__ __launch_bounds__(THREADS)
void blockgcn_main_kernel(const float* __restrict__ x, float* __restrict__ out)
{
    __shared__ __align__(16) float xs[CG][TB][NVP];    // 24576 B
    __shared__ __align__(16) float bnas[NK][NV][NVP];  //  6624 B  [k][w][v]

    const int tile = blockIdx.x;   // 0..15
    const int n    = blockIdx.y;   // 0..31
    const int h    = blockIdx.z;   // 0..7
    const int t0   = tile * TB;
    const int tid  = threadIdx.x;

    // ---- stage x tile (float4 LDG, scalar STS scatter) ----
    const float* xbase = x + ((size_t)(n * NC + h * CG)) * (NT * NV) + (size_t)t0 * NV;
    for (int idx = tid; idx < CG * TB * NV / 4; idx += THREADS) {  // 1472 float4
        int c  = idx / (TB * NV / 4);
        int r4 = idx % (TB * NV / 4);
        float4 f = ((const float4*)(xbase + (size_t)c * (NT * NV)))[r4];
        int lin = r4 * 4;
        xs[c][lin / NV][lin % NV] = f.x;  lin++;
        xs[c][lin / NV][lin % NV] = f.y;  lin++;
        xs[c][lin / NV][lin % NV] = f.z;  lin++;
        xs[c][lin / NV][lin % NV] = f.w;
    }
    for (int idx = tid; idx < CG * TB; idx += THREADS)
        xs[idx / TB][idx % TB][NV] = 0.f;

    // ---- stage BnA ([k][w][v], this h) ----
    for (int idx = tid; idx < NK * NV * NVP; idx += THREADS)
        (&bnas[0][0][0])[idx] = (&g_bna[idx / (NV * NVP)][h][0][0])[idx % (NV * NVP)];
    __syncthreads();

    {
        const int t = tid / NV;
        const int w = tid % NV;

        // Hoist all 3 BnA columns for this w, packed over v-pairs. 72 regs.
        ull b2[NK][12];
        #pragma unroll
        for (int k = 0; k < NK; k++) {
            const ulonglong2* bp = (const ulonglong2*)&bnas[k][w][0];
            #pragma unroll
            for (int q = 0; q < 6; q++) {
                ulonglong2 u = bp[q];
                b2[k][2 * q] = u.x; b2[k][2 * q + 1] = u.y;
            }
        }

        // init: folded bias + residual, packed over o-pairs
        ull acc2[8];
        #pragma unroll
        for (int q = 0; q < 8; q++)
            acc2[q] = add2(c_bias2[h * 8 + q],
                           pack2(xs[2 * q][t][w], xs[2 * q + 1][t][w]));

        #pragma unroll 4
        for (int c = 0; c < CG; c++) {
            // load x row once, use for all 3 k
            ull x2[12];
            {
                const ulonglong2* xp = (const ulonglong2*)&xs[c][t][0];
                #pragma unroll
                for (int q = 0; q < 6; q++) {
                    ulonglong2 u = xp[q];
                    x2[2 * q] = u.x; x2[2 * q + 1] = u.y;
                }
            }
            #pragma unroll
            for (int k = 0; k < NK; k++) {
                ull sk = 0ull;
                #pragma unroll
                for (int j = 0; j < 12; j++)
                    sk = fma2(x2[j], b2[k][j], sk);
                float lo, hi;
                unpack2(sk, lo, hi);
                float s = lo + hi;
                ull sp = pack2(s, s);
                const ull* wp = &c_ws2[((k * NH + h) * CG + c) * 8];
                #pragma unroll
                for (int q = 0; q < 8; q++)
                    acc2[q] = fma2(sp, wp[q], acc2[q]);
            }
        }

        // epilogue: relu + store
        float* ob = out + ((size_t)(n * NC + h * CG)) * (NT * NV)
                        + (size_t)(t0 + t) * NV + w;
        #pragma unroll
        for (int q = 0; q < 8; q++) {
            float a, b;
            unpack2(acc2[q], a, b);
            ob[(size_t)(2 * q)     * (NT * NV)] = fmaxf(a, 0.f);
            ob[(size_t)(2 * q + 1) * (NT * NV)] = fmaxf(b, 0.f);
        }
    }
}

extern "C" void kernel_launch(void* const* d_in, const int* in_sizes, int n_in,
                              void* d_out, int out_size)
{
    const float* x      = (const float*)d_in[0];
    const float* emb    = (const float*)d_in[1];
    const float* A      = (const float*)d_in[2];
    const float* conv_w = (const float*)d_in[3];
    const float* conv_b = (const float*)d_in[4];
    const float* gamma  = (const float*)d_in[5];
    const float* beta   = (const float*)d_in[6];
    const float* mean   = (const float*)d_in[7];
    const float* var    = (const float*)d_in[8];
    const int*   hop    = (const int*)d_in[9];

    int n_hop = in_sizes[1] / (NK * NH);

    precompute_kernel<<<NK * NH + 1, 256>>>(emb, A, conv_w, conv_b,
                                            gamma, beta, mean, var, hop, n_hop);

    // Mirror folded weights/bias into constant memory (async D2D, capture-legal).
    void* ws2_src = nullptr;
    void* bias2_src = nullptr;
    cudaGetSymbolAddress(&ws2_src, g_ws2);
    cudaGetSymbolAddress(&bias2_src, g_bias2);
    cudaMemcpyToSymbolAsync(c_ws2, ws2_src, sizeof(ull) * NK * NH * CG * 8, 0,
                            cudaMemcpyDeviceToDevice, 0);
    cudaMemcpyToSymbolAsync(c_bias2, bias2_src, sizeof(ull) * NH * 8, 0,
                            cudaMemcpyDeviceToDevice, 0);

    dim3 grid(NT / TB, NN, NH);
    blockgcn_main_kernel<<<grid, THREADS>>>(x, (float*)d_out);
}

// round 5
// speedup vs baseline: 1.4856x; 1.4856x over previous
#include <cuda_runtime.h>
#include <cuda_bf16.h>
#include <math.h>

// BlockGCN fused, round 5: R3 occupancy + constant-mem weights + conflict-free
// bcol + FFMA2 adjacency. out = relu(BN(sum_k conv_k(einsum(x,BnA_k))) + x)

#define NK 3
#define NH 8
#define NV 23
#define NVP 24
#define BSTRIDE 36       // bnas row stride in floats (144B; 3-way max conflict)
#define CG 16
#define NT 256
#define NN 32
#define NC 128
#define TB 16
#define THREADS 368      // 16 t x 23 w

typedef unsigned long long ull;

__device__ __forceinline__ ull fma2(ull a, ull b, ull c) {
    ull d;
    asm("fma.rn.f32x2 %0, %1, %2, %3;" : "=l"(d) : "l"(a), "l"(b), "l"(c));
    return d;
}
__device__ __forceinline__ ull add2(ull a, ull b) {
    ull d;
    asm("add.rn.f32x2 %0, %1, %2;" : "=l"(d) : "l"(a), "l"(b));
    return d;
}
__device__ __forceinline__ ull pack2(float lo, float hi) {
    ull d;
    asm("mov.b64 %0, {%1, %2};" : "=l"(d) : "f"(lo), "f"(hi));
    return d;
}
__device__ __forceinline__ void unpack2(ull v, float& lo, float& hi) {
    asm("mov.b64 {%0, %1}, %2;" : "=f"(lo), "=f"(hi) : "l"(v));
}

// Precompute outputs (device globals; no allocation).
__device__ float g_bna[NK][NH][NV][NVP];   // [k][h][w][v], v padded with 0
__device__ ull   g_ws2[NK * NH * CG * 8];  // pack(ws[o0],ws[o1]) o-pairs, BN folded
__device__ ull   g_bias2[NH * 8];          // folded bias o-pairs

// Constant mirrors (filled by async D2D copy; proven capture-legal in R4).
__constant__ ull c_ws2[NK * NH * CG * 8];  // 24 KB
__constant__ ull c_bias2[NH * 8];

__global__ void precompute_kernel(const float* __restrict__ emb,
                                  const float* __restrict__ A,
                                  const float* __restrict__ conv_w,
                                  const float* __restrict__ conv_b,
                                  const float* __restrict__ gamma,
                                  const float* __restrict__ beta,
                                  const float* __restrict__ mean,
                                  const float* __restrict__ var,
                                  const int*   __restrict__ hop,
                                  int n_hop)
{
    int b = blockIdx.x;
    int tid = threadIdx.x;
    if (b < NK * NH) {
        int k = b / NH, h = b % NH;
        int w = tid;
        if (w < NV) {
            float Bc[NV], Ac[NV];
            float sB = 0.f, sA = 0.f;
            #pragma unroll
            for (int v = 0; v < NV; v++) {
                float bb = emb[(k * NH + h) * n_hop + hop[v * NV + w]];
                float aa = A[((k * NH + h) * NV + v) * NV + w];
                Bc[v] = bb; Ac[v] = aa;
                sB += bb * bb; sA += aa * aa;
            }
            float iB = 1.f / (sqrtf(sB) + 1e-4f);
            float iA = 1.f / (sqrtf(sA) + 1e-4f);
            #pragma unroll
            for (int v = 0; v < NV; v++)
                g_bna[k][h][w][v] = Bc[v] * iB + Ac[v] * iA;
            g_bna[k][h][w][NV] = 0.f;
        }
    } else {
        for (int idx = tid; idx < NK * NH * CG * 8; idx += blockDim.x) {
            int q = idx % 8;
            int c = (idx / 8) % CG;
            int h = (idx / (8 * CG)) % NH;
            int k = idx / (8 * CG * NH);
            int och0 = h * CG + 2 * q, och1 = och0 + 1;
            float inv0 = gamma[och0] * rsqrtf(var[och0] + 1e-5f);
            float inv1 = gamma[och1] * rsqrtf(var[och1] + 1e-5f);
            float w0 = conv_w[(k * NC + och0) * CG + c] * inv0;
            float w1 = conv_w[(k * NC + och1) * CG + c] * inv1;
            g_ws2[idx] = pack2(w0, w1);
        }
        for (int idx = tid; idx < NH * 8; idx += blockDim.x) {
            int q = idx % 8, h = idx / 8;
            float bv[2];
            #pragma unroll
            for (int j = 0; j < 2; j++) {
                int och = h * CG + 2 * q + j;
                float inv = gamma[och] * rsqrtf(var[och] + 1e-5f);
                float sb = conv_b[och] + conv_b[NC + och] + conv_b[2 * NC + och];
                bv[j] = sb * inv + beta[och] - mean[och] * inv;
            }
            g_bias2[idx] = pack2(bv[0], bv[1]);
        }
    }
}

__global__ __launch_bounds__(THREADS, 2)
void blockgcn_main_kernel(const float* __restrict__ x, float* __restrict__ out)
{
    __shared__ __align__(16) float xs[CG][TB][NVP];      // 24576 B
    __shared__ __align__(16) float bnas[NK][NV][BSTRIDE]; //  9936 B  [k][w][v]

    const int tile = blockIdx.x;   // 0..15
    const int n    = blockIdx.y;   // 0..31
    const int h    = blockIdx.z;   // 0..7
    const int t0   = tile * TB;
    const int tid  = threadIdx.x;

    // ---- stage x tile (float4 LDG, scalar STS scatter) ----
    const float* xbase = x + ((size_t)(n * NC + h * CG)) * (NT * NV) + (size_t)t0 * NV;
    for (int idx = tid; idx < CG * TB * NV / 4; idx += THREADS) {  // 1472 float4
        int c  = idx / (TB * NV / 4);
        int r4 = idx % (TB * NV / 4);
        float4 f = ((const float4*)(xbase + (size_t)c * (NT * NV)))[r4];
        int lin = r4 * 4;
        xs[c][lin / NV][lin % NV] = f.x;  lin++;
        xs[c][lin / NV][lin % NV] = f.y;  lin++;
        xs[c][lin / NV][lin % NV] = f.z;  lin++;
        xs[c][lin / NV][lin % NV] = f.w;
    }
    for (int idx = tid; idx < CG * TB; idx += THREADS)
        xs[idx / TB][idx % TB][NV] = 0.f;

    // ---- stage BnA ([k][w][v] rows, stride 36 floats, this h) ----
    for (int idx = tid; idx < NK * NV * NVP; idx += THREADS) {
        int k = idx / (NV * NVP), rem = idx % (NV * NVP);
        bnas[k][rem / NVP][rem % NVP] = (&g_bna[k][h][0][0])[rem];
    }
    __syncthreads();

    {
        const int t = tid / NV;
        const int w = tid % NV;

        // init: folded bias + residual, packed over o-pairs
        ull acc2[8];
        #pragma unroll
        for (int q = 0; q < 8; q++)
            acc2[q] = add2(c_bias2[h * 8 + q],
                           pack2(xs[2 * q][t][w], xs[2 * q + 1][t][w]));

        #pragma unroll 1
        for (int k = 0; k < NK; k++) {
            // hoist this k's BnA column (v-pairs) — reused for all 16 c
            ull b2[12];
            {
                const float4* bp = (const float4*)&bnas[k][w][0];
                #pragma unroll
                for (int q = 0; q < 6; q++) {
                    float4 f = bp[q];
                    b2[2 * q]     = pack2(f.x, f.y);
                    b2[2 * q + 1] = pack2(f.z, f.w);
                }
            }
            #pragma unroll 4
            for (int c = 0; c < CG; c++) {
                // s = sum_v x[c,t,v] * bcol[v]  in packed pairs
                const ulonglong2* xp = (const ulonglong2*)&xs[c][t][0];
                ull sk = 0ull;
                #pragma unroll
                for (int q = 0; q < 6; q++) {
                    ulonglong2 u = xp[q];
                    sk = fma2(u.x, b2[2 * q],     sk);
                    sk = fma2(u.y, b2[2 * q + 1], sk);
                }
                float lo, hi;
                unpack2(sk, lo, hi);
                float s = lo + hi;
                ull sp = pack2(s, s);
                const ull* wp = &c_ws2[((k * NH + h) * CG + c) * 8];
                #pragma unroll
                for (int q = 0; q < 8; q++)
                    acc2[q] = fma2(sp, wp[q], acc2[q]);
            }
        }

        // epilogue: relu + store
        float* ob = out + ((size_t)(n * NC + h * CG)) * (NT * NV)
                        + (size_t)(t0 + t) * NV + w;
        #pragma unroll
        for (int q = 0; q < 8; q++) {
            float a, b;
            unpack2(acc2[q], a, b);
            ob[(size_t)(2 * q)     * (NT * NV)] = fmaxf(a, 0.f);
            ob[(size_t)(2 * q + 1) * (NT * NV)] = fmaxf(b, 0.f);
        }
    }
}

extern "C" void kernel_launch(void* const* d_in, const int* in_sizes, int n_in,
                              void* d_out, int out_size)
{
    const float* x      = (const float*)d_in[0];
    const float* emb    = (const float*)d_in[1];
    const float* A      = (const float*)d_in[2];
    const float* conv_w = (const float*)d_in[3];
    const float* conv_b = (const float*)d_in[4];
    const float* gamma  = (const float*)d_in[5];
    const float* beta   = (const float*)d_in[6];
    const float* mean   = (const float*)d_in[7];
    const float* var    = (const float*)d_in[8];
    const int*   hop    = (const int*)d_in[9];

    int n_hop = in_sizes[1] / (NK * NH);

    precompute_kernel<<<NK * NH + 1, 256>>>(emb, A, conv_w, conv_b,
                                            gamma, beta, mean, var, hop, n_hop);

    void* ws2_src = nullptr;
    void* bias2_src = nullptr;
    cudaGetSymbolAddress(&ws2_src, g_ws2);
    cudaGetSymbolAddress(&bias2_src, g_bias2);
    cudaMemcpyToSymbolAsync(c_ws2, ws2_src, sizeof(ull) * NK * NH * CG * 8, 0,
                            cudaMemcpyDeviceToDevice, 0);
    cudaMemcpyToSymbolAsync(c_bias2, bias2_src, sizeof(ull) * NH * 8, 0,
                            cudaMemcpyDeviceToDevice, 0);

    dim3 grid(NT / TB, NN, NH);
    blockgcn_main_kernel<<<grid, THREADS>>>(x, (float*)d_out);
}